// round 2
// baseline (speedup 1.0000x reference)
#include <cuda_runtime.h>

#define Hdim 256
#define Wdim 256
#define Cdim 64
#define UN   8
#define TR   32
#define PITCH 257
#define HSMEM (3 * TR * PITCH * 4)

// ---------------------------------------------------------------------------
// Vertical kernel: down = forward scan along H, up = backward scan along H.
// One thread per W column; two chains (down & up) interleaved for ILP.
// Loads staged 8-deep in registers so LDGs batch (high MLP).
// ---------------------------------------------------------------------------
__global__ __launch_bounds__(128) void vert_kernel(
    const float* __restrict__ x,
    const float* __restrict__ w_up,   const float* __restrict__ b_up,
    const float* __restrict__ w_down, const float* __restrict__ b_down,
    float* __restrict__ out_up, float* __restrict__ out_down)
{
    int bc = blockIdx.x >> 1;                       // (b*C + c) in [0,256)
    int w  = ((blockIdx.x & 1) << 7) + threadIdx.x; // column
    int c  = bc & (Cdim - 1);

    size_t off = (size_t)bc * (Hdim * Wdim) + w;
    const float* xp = x        + off;
    float*       od = out_down + off;
    float*       ou = out_up   + off;

    float wd = w_down[c], bd = b_down[c];
    float wu = w_up[c],   bu = b_up[c];

    float hd, hu;
    {   // peeled first chunk (handles h_0 = relu(x_0) at both ends)
        float xf[UN], xb[UN];
        #pragma unroll
        for (int j = 0; j < UN; j++) {
            xf[j] = xp[j * Wdim];
            xb[j] = xp[(Hdim - 1 - j) * Wdim];
        }
        hd = fmaxf(xf[0], 0.f); od[0] = hd;
        hu = fmaxf(xb[0], 0.f); ou[(Hdim - 1) * Wdim] = hu;
        #pragma unroll
        for (int j = 1; j < UN; j++) {
            hd = fmaxf(fmaf(wd, hd, bd + xf[j]), 0.f); od[j * Wdim] = hd;
            hu = fmaxf(fmaf(wu, hu, bu + xb[j]), 0.f); ou[(Hdim - 1 - j) * Wdim] = hu;
        }
    }
    for (int t0 = UN; t0 < Hdim; t0 += UN) {
        float sf[UN], sb[UN];
        #pragma unroll
        for (int j = 0; j < UN; j++) {          // batched independent loads;
            sf[j] = bd + xp[(t0 + j) * Wdim];   // bias folded off critical path
            sb[j] = bu + xp[(Hdim - 1 - t0 - j) * Wdim];
        }
        #pragma unroll
        for (int j = 0; j < UN; j++) {
            hd = fmaxf(fmaf(wd, hd, sf[j]), 0.f); od[(t0 + j) * Wdim] = hd;
            hu = fmaxf(fmaf(wu, hu, sb[j]), 0.f); ou[(Hdim - 1 - t0 - j) * Wdim] = hu;
        }
    }
}

// ---------------------------------------------------------------------------
// Horizontal kernel: right = forward scan along W, left = backward scan.
// Tile 32 rows x 256 cols staged in padded SMEM (conflict-free), warp 0 scans
// right, warp 1 scans left concurrently; coalesced tile load/stores.
// ---------------------------------------------------------------------------
__global__ __launch_bounds__(256) void horiz_kernel(
    const float* __restrict__ x,
    const float* __restrict__ w_right, const float* __restrict__ b_right,
    const float* __restrict__ w_left,  const float* __restrict__ b_left,
    float* __restrict__ out_right, float* __restrict__ out_left)
{
    extern __shared__ float sm[];
    float* xt = sm;                   // input tile
    float* rt = sm +     TR * PITCH;  // right results
    float* lt = sm + 2 * TR * PITCH;  // left results

    int bc = blockIdx.x >> 3;         // (b*C + c)
    int ht = blockIdx.x & 7;          // which 32-row tile of H
    int c  = bc & (Cdim - 1);

    size_t goff = (size_t)bc * (Hdim * Wdim) + (size_t)ht * (TR * Wdim);
    const float* xp = x + goff;

    // coalesced tile load into padded smem
    for (int i = threadIdx.x; i < TR * Wdim; i += 256) {
        int r = i >> 8, cw = i & 255;
        xt[r * PITCH + cw] = xp[i];
    }
    __syncthreads();

    int warp = threadIdx.x >> 5, lane = threadIdx.x & 31;
    if (warp == 0) {            // RIGHT: forward scan, one row per lane
        float wr = w_right[c], br = b_right[c];
        const float* xr = xt + lane * PITCH;
        float*       po = rt + lane * PITCH;
        float h;
        {
            float xv[UN];
            #pragma unroll
            for (int j = 0; j < UN; j++) xv[j] = xr[j];
            h = fmaxf(xv[0], 0.f); po[0] = h;
            #pragma unroll
            for (int j = 1; j < UN; j++) {
                h = fmaxf(fmaf(wr, h, br + xv[j]), 0.f); po[j] = h;
            }
        }
        for (int t0 = UN; t0 < Wdim; t0 += UN) {
            float sv[UN];
            #pragma unroll
            for (int j = 0; j < UN; j++) sv[j] = br + xr[t0 + j];
            #pragma unroll
            for (int j = 0; j < UN; j++) {
                h = fmaxf(fmaf(wr, h, sv[j]), 0.f); po[t0 + j] = h;
            }
        }
    } else if (warp == 1) {     // LEFT: backward scan
        float wl = w_left[c], bl = b_left[c];
        const float* xr = xt + lane * PITCH;
        float*       po = lt + lane * PITCH;
        float h;
        {
            float xv[UN];
            #pragma unroll
            for (int j = 0; j < UN; j++) xv[j] = xr[Wdim - 1 - j];
            h = fmaxf(xv[0], 0.f); po[Wdim - 1] = h;
            #pragma unroll
            for (int j = 1; j < UN; j++) {
                h = fmaxf(fmaf(wl, h, bl + xv[j]), 0.f); po[Wdim - 1 - j] = h;
            }
        }
        for (int t0 = UN; t0 < Wdim; t0 += UN) {
            float sv[UN];
            #pragma unroll
            for (int j = 0; j < UN; j++) sv[j] = bl + xr[Wdim - 1 - t0 - j];
            #pragma unroll
            for (int j = 0; j < UN; j++) {
                h = fmaxf(fmaf(wl, h, sv[j]), 0.f); po[Wdim - 1 - t0 - j] = h;
            }
        }
    }
    __syncthreads();

    // coalesced tile stores
    float* orp = out_right + goff;
    float* olp = out_left  + goff;
    for (int i = threadIdx.x; i < TR * Wdim; i += 256) {
        int r = i >> 8, cw = i & 255;
        orp[i] = rt[r * PITCH + cw];
        olp[i] = lt[r * PITCH + cw];
    }
}

// ---------------------------------------------------------------------------
// Launch: output order is (up, right, down, left), each B*C*H*W floats.
// ---------------------------------------------------------------------------
extern "C" void kernel_launch(void* const* d_in, const int* in_sizes, int n_in,
                              void* d_out, int out_size)
{
    const float* x       = (const float*)d_in[0];
    const float* w_up    = (const float*)d_in[1];
    const float* b_up    = (const float*)d_in[2];
    const float* w_right = (const float*)d_in[3];
    const float* b_right = (const float*)d_in[4];
    const float* w_down  = (const float*)d_in[5];
    const float* b_down  = (const float*)d_in[6];
    const float* w_left  = (const float*)d_in[7];
    const float* b_left  = (const float*)d_in[8];
    float* out = (float*)d_out;

    const size_t N = (size_t)4 * Cdim * Hdim * Wdim; // 16,777,216

    // Eager host-side attribute set (not a stream op; capture-safe).
    static int smem_ok = -1;
    if (smem_ok < 0) {
        smem_ok = (cudaFuncSetAttribute(horiz_kernel,
                     cudaFuncAttributeMaxDynamicSharedMemorySize, HSMEM)
                   == cudaSuccess) ? 1 : 0;
    }

    vert_kernel<<<512, 128>>>(x, w_up, b_up, w_down, b_down,
                              out /*up*/, out + 2 * N /*down*/);
    horiz_kernel<<<2048, 256, HSMEM>>>(x, w_right, b_right, w_left, b_left,
                                       out + N /*right*/, out + 3 * N /*left*/);
}